// round 16
// baseline (speedup 1.0000x reference)
#include <cuda_runtime.h>
#include <cstdint>

#define BB 4
#define SS 4096
#define DIN 1024
#define DOUT 64

// Projected tensors as tf32 bit patterns.
// g_q: [b][s][d] normal, pre-scaled by 0.125*log2(e).
// g_k: [b][s][d], d pair-permuted within 8-groups (logical l -> l<4?2l:2(l-4)+1).
// g_vt: [b][s_blk][d][s_in_blk] transposed, s_in_blk pair-permuted in 8-groups.
__device__ uint32_t g_q [BB * SS * DOUT];
__device__ uint32_t g_k [BB * SS * DOUT];
__device__ uint32_t g_vt[BB * SS * DOUT];

// Pre-converted, pair-permuted tf32 weights.
__device__ uint32_t g_wt[192 * DIN];

// Split-KV partial scratch: chunks of 8 KV tiles -> 288 slots per batch.
#define SLOTS_PER_B 288
__device__ float g_pO[BB * SLOTS_PER_B * 64 * 64];
__device__ float g_pm[BB * SLOTS_PER_B * 64];
__device__ float g_pl[BB * SLOTS_PER_B * 64];

// Last-CTA combine counters (self-resetting via atomicInc wrap).
__device__ unsigned int g_cnt[BB * 64];

// ---------------------------------------------------------------------------
// Helpers
// ---------------------------------------------------------------------------
__device__ __forceinline__ uint32_t f2tf(float f) {
    uint32_t r; asm("cvt.rna.tf32.f32 %0, %1;" : "=r"(r) : "f"(f)); return r;
}
__device__ __forceinline__ float ex2(float x) {
    float r; asm("ex2.approx.f32 %0, %1;" : "=f"(r) : "f"(x)); return r;
}
__device__ __forceinline__ void mma_tf32(float c[4],
    uint32_t a0, uint32_t a1, uint32_t a2, uint32_t a3,
    uint32_t b0, uint32_t b1)
{
    asm volatile(
        "mma.sync.aligned.m16n8k8.row.col.f32.tf32.tf32.f32 "
        "{%0,%1,%2,%3}, {%4,%5,%6,%7}, {%8,%9}, {%0,%1,%2,%3};"
        : "+f"(c[0]), "+f"(c[1]), "+f"(c[2]), "+f"(c[3])
        : "r"(a0), "r"(a1), "r"(a2), "r"(a3), "r"(b0), "r"(b1));
}
__device__ __forceinline__ void cpa16(uint32_t dst_smem, const void* src) {
    asm volatile("cp.async.cg.shared.global [%0], [%1], 16;"
                 :: "r"(dst_smem), "l"(src));
}
__device__ __forceinline__ void cpa_commit() {
    asm volatile("cp.async.commit_group;" ::: "memory");
}
__device__ __forceinline__ void cpa_wait0() {
    asm volatile("cp.async.wait_group 0;" ::: "memory");
}

// ---------------------------------------------------------------------------
// W prep: convert to tf32 bits, pair-permute each 8-group along k.
// ---------------------------------------------------------------------------
__global__ __launch_bounds__(256) void prep_w_kernel(
    const float* __restrict__ Wq,
    const float* __restrict__ Wk,
    const float* __restrict__ Wv)
{
    int gidx = blockIdx.x * 256 + threadIdx.x;   // 0..24575
    int row = gidx >> 7;          // 0..191
    int grp = gidx & 127;         // 8-word group along k
    const float* W = (row < 64) ? Wq : (row < 128) ? Wk : Wv;
    const float* src = &W[(size_t)(row & 63) * DIN + grp * 8];
    float4 v0 = *(const float4*)src;
    float4 v1 = *(const float4*)(src + 4);
    uint32_t* dst = &g_wt[(size_t)row * DIN + grp * 8];
    // physical [0..7] = logical [0,4,1,5,2,6,3,7]
    *(uint4*)dst       = make_uint4(f2tf(v0.x), f2tf(v1.x), f2tf(v0.y), f2tf(v1.y));
    *(uint4*)(dst + 4) = make_uint4(f2tf(v0.z), f2tf(v1.z), f2tf(v0.w), f2tf(v1.w));
}

// ---------------------------------------------------------------------------
// Fused QKV projection (R11-proven config). Grid 256, 256 threads,
// pair-interleaved smem (stride 40), W via cp.async, double-buffered.
// ---------------------------------------------------------------------------
#define PJ_S 40
#define XS_W (64 * PJ_S)     // 2560 words per stage
#define WS_W (192 * PJ_S)    // 7680 words per stage
#define PROJ_SMEM_BYTES (2 * (XS_W + WS_W) * 4)   // 81920

__global__ __launch_bounds__(256) void proj_kernel(const float* __restrict__ x)
{
    extern __shared__ uint32_t psm[];
    const uint32_t sm_base = (uint32_t)__cvta_generic_to_shared(psm);
    const uint32_t ws_base = sm_base + 2 * XS_W * 4;

    const int tid  = threadIdx.x;
    const int warp = tid >> 5, lane = tid & 31;
    const int lr = lane >> 2, lc = lane & 3;
    const int m0 = blockIdx.x * 64;
    const int mrow  = (warp & 3) * 16;
    const int nbase = (warp >> 2) * 12;    // n-tile base: 0 or 12

    const int xrow = tid >> 2, xgrp = tid & 3;

    float c[12][4];
    #pragma unroll
    for (int i = 0; i < 12; i++)
        c[i][0] = c[i][1] = c[i][2] = c[i][3] = 0.f;

    float4 xa, xb;
    auto ldgx = [&](int k0) {
        const float* p = &x[(size_t)(m0 + xrow) * DIN + k0 + xgrp * 8];
        xa = *(const float4*)p;
        xb = *(const float4*)(p + 4);
    };
    auto stsx = [&](int s) {
        uint32_t* X = psm + s * XS_W + xrow * PJ_S + xgrp * 8;
        *(uint4*)X       = make_uint4(f2tf(xa.x), f2tf(xb.x), f2tf(xa.y), f2tf(xb.y));
        *(uint4*)(X + 4) = make_uint4(f2tf(xa.z), f2tf(xb.z), f2tf(xa.w), f2tf(xb.w));
    };
    auto cpaw = [&](int k0, int s) {
        uint32_t sb = ws_base + s * WS_W * 4;
        #pragma unroll
        for (int it = 0; it < 6; it++) {
            int idx = tid + it * 256;
            int row = idx >> 3, rem = idx & 7;
            int grp = rem >> 1, half = rem & 1;
            cpa16(sb + (row * PJ_S + grp * 8 + half * 4) * 4,
                  g_wt + (size_t)row * DIN + k0 + grp * 8 + half * 4);
        }
        cpa_commit();
    };

    ldgx(0);
    cpaw(0, 0);

    for (int kc = 0; kc < 32; kc++) {
        const int s = kc & 1;
        stsx(s);
        if (kc + 1 < 32) ldgx((kc + 1) * 32);
        cpa_wait0();
        __syncthreads();
        if (kc + 1 < 32) cpaw((kc + 1) * 32, s ^ 1);

        const uint32_t* Xs = psm + s * XS_W;
        const uint32_t* Ws = psm + 2 * XS_W + s * WS_W;

        #pragma unroll
        for (int ks = 0; ks < 4; ks++) {
            int kk = ks * 8;
            uint2 a0 = *(const uint2*)&Xs[(mrow + lr) * PJ_S + kk + 2 * lc];
            uint2 a1 = *(const uint2*)&Xs[(mrow + lr + 8) * PJ_S + kk + 2 * lc];
            #pragma unroll
            for (int nt = 0; nt < 12; nt++) {
                int brow = (nbase + nt) * 8 + lr;
                uint2 b = *(const uint2*)&Ws[brow * PJ_S + kk + 2 * lc];
                mma_tf32(c[nt], a0.x, a1.x, a0.y, a1.y, b.x, b.y);
            }
        }
        __syncthreads();
    }

    const float qscale = 0.125f * 1.44269504f;   // 1/sqrt(64) * log2(e)
    const int l0 = 2 * lc, l1 = 2 * lc + 1;
    const int p0 = (l0 < 4) ? 2 * l0 : 2 * (l0 - 4) + 1;
    const int p1 = (l1 < 4) ? 2 * l1 : 2 * (l1 - 4) + 1;
    const int pmlr = (lr < 4) ? 2 * lr : 2 * (lr - 4) + 1;
    const size_t vbase = (size_t)(m0 >> 6) * 64 * 64;

    #pragma unroll
    for (int nt = 0; nt < 12; nt++) {
        int g = nbase + nt;   // global n-tile 0..23
        if (g < 8) {
            int col = g * 8 + 2 * lc;
            size_t r0 = (size_t)(m0 + mrow + lr) * DOUT + col;
            *(uint2*)&g_q[r0] =
                make_uint2(f2tf(c[nt][0] * qscale), f2tf(c[nt][1] * qscale));
            *(uint2*)&g_q[r0 + 8 * DOUT] =
                make_uint2(f2tf(c[nt][2] * qscale), f2tf(c[nt][3] * qscale));
        } else if (g < 16) {
            int ntl = g - 8;
            size_t r0 = (size_t)(m0 + mrow + lr) * DOUT + ntl * 8;
            g_k[r0 + p0]            = f2tf(c[nt][0]);
            g_k[r0 + p1]            = f2tf(c[nt][1]);
            g_k[r0 + 8 * DOUT + p0] = f2tf(c[nt][2]);
            g_k[r0 + 8 * DOUT + p1] = f2tf(c[nt][3]);
        } else {
            int d0 = (g - 16) * 8 + 2 * lc;
            g_vt[vbase + (size_t)d0 * 64       + mrow + pmlr]     = f2tf(c[nt][0]);
            g_vt[vbase + (size_t)(d0 + 1) * 64 + mrow + pmlr]     = f2tf(c[nt][1]);
            g_vt[vbase + (size_t)d0 * 64       + mrow + 8 + pmlr] = f2tf(c[nt][2]);
            g_vt[vbase + (size_t)(d0 + 1) * 64 + mrow + 8 + pmlr] = f2tf(c[nt][3]);
        }
    }
}

// ---------------------------------------------------------------------------
// slot base for (qb): chunks of 8 KV tiles.
// ---------------------------------------------------------------------------
__device__ __forceinline__ int slot_base(int qb) {
    if (qb < 8)  return qb;
    if (qb < 16) return 8   + (qb - 8)  * 2;
    if (qb < 24) return 24  + (qb - 16) * 3;
    if (qb < 32) return 48  + (qb - 24) * 4;
    if (qb < 40) return 80  + (qb - 32) * 5;
    if (qb < 48) return 120 + (qb - 40) * 6;
    if (qb < 56) return 168 + (qb - 48) * 7;
    return 224 + (qb - 56) * 8;
}

// ---------------------------------------------------------------------------
// Flash attention, split-KV (chunks of 8 KV tiles). Grid 1152 = 4b x 288 slots.
// Fused last-CTA combine: the final chunk CTA of each (b,qb) row merges all
// partials and writes `out` (threadFenceReduction pattern; counter wraps).
// ---------------------------------------------------------------------------
#define KT_S 72
#define STAGE_WORDS (2 * 64 * KT_S)
#define ATTN_SMEM_BYTES (2 * STAGE_WORDS * 4)   // 73728

__global__ __launch_bounds__(128, 3) void attn_kernel(float* __restrict__ out)
{
    extern __shared__ uint32_t sm[];
    __shared__ unsigned int s_last;

    const int tid  = threadIdx.x;
    const int warp = tid >> 5, lane = tid & 31;
    const int lr = lane >> 2, lc = lane & 3;
    const bool odd = lc & 1;
    const int srcA = (lane & 28) | (lc >> 1);
    const int srcB = srcA + 2;

    const int bb = blockIdx.x & 3;
    const int t  = 287 - (blockIdx.x >> 2);   // slot index; big work first
    int qb, ch;
    if (t < 8)        { qb = t;                         ch = 0; }
    else if (t < 24)  { int u = t - 8;   qb = 8  + (u >> 1); ch = u & 1; }
    else if (t < 48)  { int u = t - 24;  int q = u / 3; qb = 16 + q; ch = u - 3 * q; }
    else if (t < 80)  { int u = t - 48;  qb = 24 + (u >> 2); ch = u & 3; }
    else if (t < 120) { int u = t - 80;  int q = u / 5; qb = 32 + q; ch = u - 5 * q; }
    else if (t < 168) { int u = t - 120; int q = u / 6; qb = 40 + q; ch = u - 6 * q; }
    else if (t < 224) { int u = t - 168; int q = u / 7; qb = 48 + q; ch = u - 7 * q; }
    else              { int u = t - 224; qb = 56 + (u >> 3); ch = u & 7; }
    const int nch = (qb >> 3) + 1;
    const int q0  = qb * 64;
    const int kb0 = ch * 8;
    const int kbE = min(kb0 + 8, qb + 1);

    const uint32_t* __restrict__ qg  = g_q  + ((size_t)bb * SS + q0) * DOUT;
    const uint32_t* __restrict__ kg  = g_k  + (size_t)bb * SS * DOUT;
    const uint32_t* __restrict__ vtg = g_vt + (size_t)bb * SS * DOUT;

    const uint32_t sm_base = (uint32_t)__cvta_generic_to_shared(sm);
    const int ldrow = tid >> 4;
    const int ldc4  = (tid & 15) * 4;

    // prologue: stage 0 loads tile kb0
    {
        uint32_t kdst  = sm_base;
        uint32_t vtdst = sm_base + 64 * KT_S * 4;
        const uint32_t* ksrc  = kg  + (size_t)kb0 * 64 * DOUT;
        const uint32_t* vtsrc = vtg + (size_t)kb0 * 64 * DOUT;
        #pragma unroll
        for (int it = 0; it < 8; it++) {
            int row = ldrow + it * 8;
            cpa16(kdst  + (row * KT_S + ldc4) * 4, ksrc  + (size_t)row * DOUT + ldc4);
            cpa16(vtdst + (row * KT_S + ldc4) * 4, vtsrc + (size_t)row * DOUT + ldc4);
        }
        cpa_commit();
    }

    // Q fragments (already tf32 + scaled)
    uint32_t qa[8][4];
    #pragma unroll
    for (int kc = 0; kc < 8; kc++) {
        int col = kc * 8 + lc;
        qa[kc][0] = qg[(warp * 16 + lr) * DOUT + col];
        qa[kc][1] = qg[(warp * 16 + lr + 8) * DOUT + col];
        qa[kc][2] = qg[(warp * 16 + lr) * DOUT + col + 4];
        qa[kc][3] = qg[(warp * 16 + lr + 8) * DOUT + col + 4];
    }

    float o[8][4];
    #pragma unroll
    for (int nt = 0; nt < 8; nt++)
        o[nt][0] = o[nt][1] = o[nt][2] = o[nt][3] = 0.f;
    float m0r = -1e30f, m1r = -1e30f, l0r = 0.f, l1r = 0.f;

    cpa_wait0();
    __syncthreads();

    for (int kb = kb0; kb < kbE; kb++) {
        if (kb > kb0) { cpa_wait0(); __syncthreads(); }

        if (kb + 1 < kbE) {
            const int kn = (kb + 1) * 64;
            uint32_t sb    = sm_base + ((kb + 1) & 1) * STAGE_WORDS * 4;
            uint32_t kdst  = sb;
            uint32_t vtdst = sb + 64 * KT_S * 4;
            const uint32_t* ksrc  = kg  + (size_t)kn * DOUT;
            const uint32_t* vtsrc = vtg + (size_t)kn * DOUT;
            #pragma unroll
            for (int it = 0; it < 8; it++) {
                int row = ldrow + it * 8;
                cpa16(kdst  + (row * KT_S + ldc4) * 4, ksrc  + (size_t)row * DOUT + ldc4);
                cpa16(vtdst + (row * KT_S + ldc4) * 4, vtsrc + (size_t)row * DOUT + ldc4);
            }
            cpa_commit();
        }

        const uint32_t* Ks = sm + (kb & 1) * STAGE_WORDS;
        const uint32_t* VT = Ks + 64 * KT_S;

        // S = Q K^T
        float sf[8][4];
        #pragma unroll
        for (int nt = 0; nt < 8; nt++)
            sf[nt][0] = sf[nt][1] = sf[nt][2] = sf[nt][3] = 0.f;
        #pragma unroll
        for (int kc = 0; kc < 8; kc++) {
            #pragma unroll
            for (int nt = 0; nt < 8; nt++) {
                uint2 b = *(const uint2*)&Ks[(nt * 8 + lr) * KT_S + kc * 8 + 2 * lc];
                mma_tf32(sf[nt], qa[kc][0], qa[kc][1], qa[kc][2], qa[kc][3], b.x, b.y);
            }
        }

        // causal mask on the diagonal tile
        if (kb == qb) {
            int row0 = q0 + warp * 16 + lr;
            int row1 = row0 + 8;
            const int k0c = kb * 64;
            #pragma unroll
            for (int nt = 0; nt < 8; nt++) {
                int cb = k0c + nt * 8 + 2 * lc;
                if (cb     > row0) sf[nt][0] = -1e30f;
                if (cb + 1 > row0) sf[nt][1] = -1e30f;
                if (cb     > row1) sf[nt][2] = -1e30f;
                if (cb + 1 > row1) sf[nt][3] = -1e30f;
            }
        }

        // online softmax (exp2 space)
        float t0 = -1e30f, t1 = -1e30f;
        #pragma unroll
        for (int nt = 0; nt < 8; nt++) {
            t0 = fmaxf(t0, fmaxf(sf[nt][0], sf[nt][1]));
            t1 = fmaxf(t1, fmaxf(sf[nt][2], sf[nt][3]));
        }
        t0 = fmaxf(t0, __shfl_xor_sync(0xffffffffu, t0, 1));
        t0 = fmaxf(t0, __shfl_xor_sync(0xffffffffu, t0, 2));
        t1 = fmaxf(t1, __shfl_xor_sync(0xffffffffu, t1, 1));
        t1 = fmaxf(t1, __shfl_xor_sync(0xffffffffu, t1, 2));
        float mn0 = fmaxf(m0r, t0), mn1 = fmaxf(m1r, t1);
        float cor0 = ex2(m0r - mn0), cor1 = ex2(m1r - mn1);
        float rs0 = 0.f, rs1 = 0.f;
        #pragma unroll
        for (int nt = 0; nt < 8; nt++) {
            float p00 = ex2(sf[nt][0] - mn0), p01 = ex2(sf[nt][1] - mn0);
            float p10 = ex2(sf[nt][2] - mn1), p11 = ex2(sf[nt][3] - mn1);
            rs0 += p00 + p01; rs1 += p10 + p11;
            sf[nt][0] = __uint_as_float(f2tf(p00));
            sf[nt][1] = __uint_as_float(f2tf(p01));
            sf[nt][2] = __uint_as_float(f2tf(p10));
            sf[nt][3] = __uint_as_float(f2tf(p11));
            o[nt][0] *= cor0; o[nt][1] *= cor0;
            o[nt][2] *= cor1; o[nt][3] *= cor1;
        }
        rs0 += __shfl_xor_sync(0xffffffffu, rs0, 1);
        rs0 += __shfl_xor_sync(0xffffffffu, rs0, 2);
        rs1 += __shfl_xor_sync(0xffffffffu, rs1, 1);
        rs1 += __shfl_xor_sync(0xffffffffu, rs1, 2);
        l0r = l0r * cor0 + rs0; l1r = l1r * cor1 + rs1;
        m0r = mn0; m1r = mn1;

        // O += P V — P A-frags via quad shuffles
        #pragma unroll
        for (int kc = 0; kc < 8; kc++) {
            float s0 = __shfl_sync(0xffffffffu, sf[kc][0], srcA);
            float s1 = __shfl_sync(0xffffffffu, sf[kc][1], srcA);
            float s2 = __shfl_sync(0xffffffffu, sf[kc][2], srcA);
            float s3 = __shfl_sync(0xffffffffu, sf[kc][3], srcA);
            float u0 = __shfl_sync(0xffffffffu, sf[kc][0], srcB);
            float u1 = __shfl_sync(0xffffffffu, sf[kc][1], srcB);
            float u2 = __shfl_sync(0xffffffffu, sf[kc][2], srcB);
            float u3 = __shfl_sync(0xffffffffu, sf[kc][3], srcB);
            uint32_t a0 = __float_as_uint(odd ? s1 : s0);
            uint32_t a1 = __float_as_uint(odd ? s3 : s2);
            uint32_t a2 = __float_as_uint(odd ? u1 : u0);
            uint32_t a3 = __float_as_uint(odd ? u3 : u2);
            #pragma unroll
            for (int nt = 0; nt < 8; nt++) {
                uint2 b = *(const uint2*)&VT[(nt * 8 + lr) * KT_S + kc * 8 + 2 * lc];
                mma_tf32(o[nt], a0, a1, a2, a3, b.x, b.y);
            }
        }
    }

    if (nch == 1) {
        float inv0 = 1.f / l0r, inv1 = 1.f / l1r;
        #pragma unroll
        for (int nt = 0; nt < 8; nt++) {
            int col = nt * 8 + 2 * lc;
            size_t r0 = ((size_t)bb * SS + q0 + warp * 16 + lr) * DOUT + col;
            *(float2*)&out[r0]            = make_float2(o[nt][0] * inv0, o[nt][1] * inv0);
            *(float2*)&out[r0 + 8 * DOUT] = make_float2(o[nt][2] * inv1, o[nt][3] * inv1);
        }
        return;
    }

    // ---- multi-chunk: write partial, then last CTA combines ----
    const int base = bb * SLOTS_PER_B + slot_base(qb);
    {
        const int slot = base + ch;
        float* pO = g_pO + (size_t)slot * 64 * 64;
        const int lrow0 = warp * 16 + lr, lrow1 = lrow0 + 8;
        #pragma unroll
        for (int nt = 0; nt < 8; nt++) {
            int col = nt * 8 + 2 * lc;
            *(float2*)&pO[lrow0 * 64 + col] = make_float2(o[nt][0], o[nt][1]);
            *(float2*)&pO[lrow1 * 64 + col] = make_float2(o[nt][2], o[nt][3]);
        }
        if (lc == 0) {
            g_pm[slot * 64 + lrow0] = m0r;
            g_pm[slot * 64 + lrow1] = m1r;
            g_pl[slot * 64 + lrow0] = l0r;
            g_pl[slot * 64 + lrow1] = l1r;
        }
    }

    __threadfence();
    __syncthreads();
    if (tid == 0) {
        unsigned int old = atomicInc(&g_cnt[bb * 64 + qb], (unsigned)(nch - 1));
        s_last = (old == (unsigned)(nch - 1)) ? 1u : 0u;
    }
    __syncthreads();
    if (!s_last) return;

    // Last CTA for this (bb, qb): combine all nch partials.
    #pragma unroll 2
    for (int it = 0; it < 8; it++) {
        int task = tid + it * 128;               // 1024 tasks: 64 rows x 16 f4
        int row = task >> 4;
        int cg  = (task & 15) * 4;

        float M = -1e30f;
        float mv[8];
        #pragma unroll 4
        for (int c = 0; c < nch; c++) {
            mv[c] = g_pm[(base + c) * 64 + row];
            M = fmaxf(M, mv[c]);
        }
        float L = 0.f;
        float wv[8];
        #pragma unroll 4
        for (int c = 0; c < nch; c++) {
            wv[c] = ex2(mv[c] - M);
            L += wv[c] * g_pl[(base + c) * 64 + row];
        }
        float4 acc = make_float4(0.f, 0.f, 0.f, 0.f);
        #pragma unroll 4
        for (int c = 0; c < nch; c++) {
            float4 v = *(const float4*)&g_pO[(size_t)(base + c) * 64 * 64 + row * 64 + cg];
            float w = wv[c];
            acc.x += w * v.x; acc.y += w * v.y;
            acc.z += w * v.z; acc.w += w * v.w;
        }
        float inv = 1.f / L;
        float* dst = out + ((size_t)bb * SS + q0 + row) * DOUT + cg;
        *(float4*)dst = make_float4(acc.x * inv, acc.y * inv, acc.z * inv, acc.w * inv);
    }
}

// ---------------------------------------------------------------------------
extern "C" void kernel_launch(void* const* d_in, const int* in_sizes, int n_in,
                              void* d_out, int out_size)
{
    const float* x  = (const float*)d_in[0];
    const float* Wq = (const float*)d_in[1];
    const float* Wk = (const float*)d_in[2];
    const float* Wv = (const float*)d_in[3];
    float* out = (float*)d_out;

    prep_w_kernel<<<dim3(96), 256>>>(Wq, Wk, Wv);

    cudaFuncSetAttribute(proj_kernel,
                         cudaFuncAttributeMaxDynamicSharedMemorySize,
                         PROJ_SMEM_BYTES);
    proj_kernel<<<dim3((BB * SS) / 64), 256, PROJ_SMEM_BYTES>>>(x);

    cudaFuncSetAttribute(attn_kernel,
                         cudaFuncAttributeMaxDynamicSharedMemorySize,
                         ATTN_SMEM_BYTES);
    attn_kernel<<<dim3(BB * SLOTS_PER_B), 128, ATTN_SMEM_BYTES>>>(out);
}

// round 17
// speedup vs baseline: 1.1751x; 1.1751x over previous
#include <cuda_runtime.h>
#include <cstdint>

#define BB 4
#define SS 4096
#define DIN 1024
#define DOUT 64

// Projected tensors as tf32 bit patterns.
// g_q: [b][s][d] normal, pre-scaled by 0.125*log2(e).
// g_k: [b][s][d], d pair-permuted within 8-groups (logical l -> l<4?2l:2(l-4)+1).
// g_vt: [b][s_blk][d][s_in_blk] transposed, s_in_blk pair-permuted in 8-groups.
__device__ uint32_t g_q [BB * SS * DOUT];
__device__ uint32_t g_k [BB * SS * DOUT];
__device__ uint32_t g_vt[BB * SS * DOUT];

// Pre-converted, pair-permuted tf32 weights: rows 0-63 = Wq, 64-127 = Wk,
// 128-191 = Wv; within each 8-group along k, words are pair-interleaved.
__device__ uint32_t g_wt[192 * DIN];

// Split-KV partial scratch: chunks of 8 KV tiles -> 288 slots per batch.
#define SLOTS_PER_B 288
__device__ float g_pO[BB * SLOTS_PER_B * 64 * 64];
__device__ float g_pm[BB * SLOTS_PER_B * 64];
__device__ float g_pl[BB * SLOTS_PER_B * 64];

// ---------------------------------------------------------------------------
// Helpers
// ---------------------------------------------------------------------------
__device__ __forceinline__ uint32_t f2tf(float f) {
    uint32_t r; asm("cvt.rna.tf32.f32 %0, %1;" : "=r"(r) : "f"(f)); return r;
}
__device__ __forceinline__ float ex2(float x) {
    float r; asm("ex2.approx.f32 %0, %1;" : "=f"(r) : "f"(x)); return r;
}
__device__ __forceinline__ void mma_tf32(float c[4],
    uint32_t a0, uint32_t a1, uint32_t a2, uint32_t a3,
    uint32_t b0, uint32_t b1)
{
    asm volatile(
        "mma.sync.aligned.m16n8k8.row.col.f32.tf32.tf32.f32 "
        "{%0,%1,%2,%3}, {%4,%5,%6,%7}, {%8,%9}, {%0,%1,%2,%3};"
        : "+f"(c[0]), "+f"(c[1]), "+f"(c[2]), "+f"(c[3])
        : "r"(a0), "r"(a1), "r"(a2), "r"(a3), "r"(b0), "r"(b1));
}
__device__ __forceinline__ void cpa16(uint32_t dst_smem, const void* src) {
    asm volatile("cp.async.cg.shared.global [%0], [%1], 16;"
                 :: "r"(dst_smem), "l"(src));
}
__device__ __forceinline__ void cpa_commit() {
    asm volatile("cp.async.commit_group;" ::: "memory");
}
__device__ __forceinline__ void cpa_wait0() {
    asm volatile("cp.async.wait_group 0;" ::: "memory");
}

// ---------------------------------------------------------------------------
// W prep: convert to tf32 bits, pair-permute each 8-group along k.
// Grid 384 x 64 threads (was 96 x 256 -> 0.65 CTA/SM, latency-starved).
// ---------------------------------------------------------------------------
__global__ __launch_bounds__(64) void prep_w_kernel(
    const float* __restrict__ Wq,
    const float* __restrict__ Wk,
    const float* __restrict__ Wv)
{
    int gidx = blockIdx.x * 64 + threadIdx.x;   // 0..24575
    int row = gidx >> 7;          // 0..191
    int grp = gidx & 127;         // 8-word group along k
    const float* W = (row < 64) ? Wq : (row < 128) ? Wk : Wv;
    const float* src = &W[(size_t)(row & 63) * DIN + grp * 8];
    float4 v0 = *(const float4*)src;
    float4 v1 = *(const float4*)(src + 4);
    uint32_t* dst = &g_wt[(size_t)row * DIN + grp * 8];
    // physical [0..7] = logical [0,4,1,5,2,6,3,7]
    *(uint4*)dst       = make_uint4(f2tf(v0.x), f2tf(v1.x), f2tf(v0.y), f2tf(v1.y));
    *(uint4*)(dst + 4) = make_uint4(f2tf(v0.z), f2tf(v1.z), f2tf(v0.w), f2tf(v1.w));
}

// ---------------------------------------------------------------------------
// Fused QKV projection (R11-proven). Grid 256, 256 threads, pair-interleaved
// smem (stride 40), W via cp.async from g_wt, double-buffered stages.
// ---------------------------------------------------------------------------
#define PJ_S 40
#define XS_W (64 * PJ_S)     // 2560 words per stage
#define WS_W (192 * PJ_S)    // 7680 words per stage
#define PROJ_SMEM_BYTES (2 * (XS_W + WS_W) * 4)   // 81920

__global__ __launch_bounds__(256) void proj_kernel(const float* __restrict__ x)
{
    extern __shared__ uint32_t psm[];
    const uint32_t sm_base = (uint32_t)__cvta_generic_to_shared(psm);
    const uint32_t ws_base = sm_base + 2 * XS_W * 4;

    const int tid  = threadIdx.x;
    const int warp = tid >> 5, lane = tid & 31;
    const int lr = lane >> 2, lc = lane & 3;
    const int m0 = blockIdx.x * 64;
    const int mrow  = (warp & 3) * 16;
    const int nbase = (warp >> 2) * 12;    // n-tile base: 0 or 12

    const int xrow = tid >> 2, xgrp = tid & 3;

    float c[12][4];
    #pragma unroll
    for (int i = 0; i < 12; i++)
        c[i][0] = c[i][1] = c[i][2] = c[i][3] = 0.f;

    float4 xa, xb;
    auto ldgx = [&](int k0) {
        const float* p = &x[(size_t)(m0 + xrow) * DIN + k0 + xgrp * 8];
        xa = *(const float4*)p;
        xb = *(const float4*)(p + 4);
    };
    auto stsx = [&](int s) {
        uint32_t* X = psm + s * XS_W + xrow * PJ_S + xgrp * 8;
        *(uint4*)X       = make_uint4(f2tf(xa.x), f2tf(xb.x), f2tf(xa.y), f2tf(xb.y));
        *(uint4*)(X + 4) = make_uint4(f2tf(xa.z), f2tf(xb.z), f2tf(xa.w), f2tf(xb.w));
    };
    auto cpaw = [&](int k0, int s) {
        uint32_t sb = ws_base + s * WS_W * 4;
        #pragma unroll
        for (int it = 0; it < 6; it++) {
            int idx = tid + it * 256;
            int row = idx >> 3, rem = idx & 7;
            int grp = rem >> 1, half = rem & 1;
            cpa16(sb + (row * PJ_S + grp * 8 + half * 4) * 4,
                  g_wt + (size_t)row * DIN + k0 + grp * 8 + half * 4);
        }
        cpa_commit();
    };

    ldgx(0);
    cpaw(0, 0);

    for (int kc = 0; kc < 32; kc++) {
        const int s = kc & 1;
        stsx(s);
        if (kc + 1 < 32) ldgx((kc + 1) * 32);
        cpa_wait0();
        __syncthreads();
        if (kc + 1 < 32) cpaw((kc + 1) * 32, s ^ 1);

        const uint32_t* Xs = psm + s * XS_W;
        const uint32_t* Ws = psm + 2 * XS_W + s * WS_W;

        #pragma unroll
        for (int ks = 0; ks < 4; ks++) {
            int kk = ks * 8;
            uint2 a0 = *(const uint2*)&Xs[(mrow + lr) * PJ_S + kk + 2 * lc];
            uint2 a1 = *(const uint2*)&Xs[(mrow + lr + 8) * PJ_S + kk + 2 * lc];
            #pragma unroll
            for (int nt = 0; nt < 12; nt++) {
                int brow = (nbase + nt) * 8 + lr;
                uint2 b = *(const uint2*)&Ws[brow * PJ_S + kk + 2 * lc];
                mma_tf32(c[nt], a0.x, a1.x, a0.y, a1.y, b.x, b.y);
            }
        }
        __syncthreads();
    }

    const float qscale = 0.125f * 1.44269504f;   // 1/sqrt(64) * log2(e)
    const int l0 = 2 * lc, l1 = 2 * lc + 1;
    const int p0 = (l0 < 4) ? 2 * l0 : 2 * (l0 - 4) + 1;
    const int p1 = (l1 < 4) ? 2 * l1 : 2 * (l1 - 4) + 1;
    const int pmlr = (lr < 4) ? 2 * lr : 2 * (lr - 4) + 1;
    const size_t vbase = (size_t)(m0 >> 6) * 64 * 64;

    #pragma unroll
    for (int nt = 0; nt < 12; nt++) {
        int g = nbase + nt;   // global n-tile 0..23
        if (g < 8) {
            int col = g * 8 + 2 * lc;
            size_t r0 = (size_t)(m0 + mrow + lr) * DOUT + col;
            *(uint2*)&g_q[r0] =
                make_uint2(f2tf(c[nt][0] * qscale), f2tf(c[nt][1] * qscale));
            *(uint2*)&g_q[r0 + 8 * DOUT] =
                make_uint2(f2tf(c[nt][2] * qscale), f2tf(c[nt][3] * qscale));
        } else if (g < 16) {
            int ntl = g - 8;
            size_t r0 = (size_t)(m0 + mrow + lr) * DOUT + ntl * 8;
            g_k[r0 + p0]            = f2tf(c[nt][0]);
            g_k[r0 + p1]            = f2tf(c[nt][1]);
            g_k[r0 + 8 * DOUT + p0] = f2tf(c[nt][2]);
            g_k[r0 + 8 * DOUT + p1] = f2tf(c[nt][3]);
        } else {
            int d0 = (g - 16) * 8 + 2 * lc;
            g_vt[vbase + (size_t)d0 * 64       + mrow + pmlr]     = f2tf(c[nt][0]);
            g_vt[vbase + (size_t)(d0 + 1) * 64 + mrow + pmlr]     = f2tf(c[nt][1]);
            g_vt[vbase + (size_t)d0 * 64       + mrow + 8 + pmlr] = f2tf(c[nt][2]);
            g_vt[vbase + (size_t)(d0 + 1) * 64 + mrow + 8 + pmlr] = f2tf(c[nt][3]);
        }
    }
}

// ---------------------------------------------------------------------------
// Flash attention, split-KV (chunks of 8 KV tiles). Grid 1152 = 4b x 288 slots.
// (R11 configuration: PV A-frags via quad shuffles.)
// ---------------------------------------------------------------------------
#define KT_S 72
#define STAGE_WORDS (2 * 64 * KT_S)
#define ATTN_SMEM_BYTES (2 * STAGE_WORDS * 4)   // 73728

__global__ __launch_bounds__(128, 3) void attn_kernel(float* __restrict__ out)
{
    extern __shared__ uint32_t sm[];

    const int tid  = threadIdx.x;
    const int warp = tid >> 5, lane = tid & 31;
    const int lr = lane >> 2, lc = lane & 3;
    const bool odd = lc & 1;
    const int srcA = (lane & 28) | (lc >> 1);
    const int srcB = srcA + 2;

    const int bb = blockIdx.x & 3;
    const int t  = 287 - (blockIdx.x >> 2);   // slot index; big work first
    int qb, ch;
    if (t < 8)        { qb = t;                         ch = 0; }
    else if (t < 24)  { int u = t - 8;   qb = 8  + (u >> 1); ch = u & 1; }
    else if (t < 48)  { int u = t - 24;  int q = u / 3; qb = 16 + q; ch = u - 3 * q; }
    else if (t < 80)  { int u = t - 48;  qb = 24 + (u >> 2); ch = u & 3; }
    else if (t < 120) { int u = t - 80;  int q = u / 5; qb = 32 + q; ch = u - 5 * q; }
    else if (t < 168) { int u = t - 120; int q = u / 6; qb = 40 + q; ch = u - 6 * q; }
    else if (t < 224) { int u = t - 168; int q = u / 7; qb = 48 + q; ch = u - 7 * q; }
    else              { int u = t - 224; qb = 56 + (u >> 3); ch = u & 7; }
    const int nch = (qb >> 3) + 1;
    const int q0  = qb * 64;
    const int kb0 = ch * 8;
    const int kbE = min(kb0 + 8, qb + 1);

    const uint32_t* __restrict__ qg  = g_q  + ((size_t)bb * SS + q0) * DOUT;
    const uint32_t* __restrict__ kg  = g_k  + (size_t)bb * SS * DOUT;
    const uint32_t* __restrict__ vtg = g_vt + (size_t)bb * SS * DOUT;

    const uint32_t sm_base = (uint32_t)__cvta_generic_to_shared(sm);
    const int ldrow = tid >> 4;
    const int ldc4  = (tid & 15) * 4;

    // prologue: stage 0 loads tile kb0
    {
        uint32_t kdst  = sm_base;
        uint32_t vtdst = sm_base + 64 * KT_S * 4;
        const uint32_t* ksrc  = kg  + (size_t)kb0 * 64 * DOUT;
        const uint32_t* vtsrc = vtg + (size_t)kb0 * 64 * DOUT;
        #pragma unroll
        for (int it = 0; it < 8; it++) {
            int row = ldrow + it * 8;
            cpa16(kdst  + (row * KT_S + ldc4) * 4, ksrc  + (size_t)row * DOUT + ldc4);
            cpa16(vtdst + (row * KT_S + ldc4) * 4, vtsrc + (size_t)row * DOUT + ldc4);
        }
        cpa_commit();
    }

    // Q fragments (already tf32 + scaled)
    uint32_t qa[8][4];
    #pragma unroll
    for (int kc = 0; kc < 8; kc++) {
        int col = kc * 8 + lc;
        qa[kc][0] = qg[(warp * 16 + lr) * DOUT + col];
        qa[kc][1] = qg[(warp * 16 + lr + 8) * DOUT + col];
        qa[kc][2] = qg[(warp * 16 + lr) * DOUT + col + 4];
        qa[kc][3] = qg[(warp * 16 + lr + 8) * DOUT + col + 4];
    }

    float o[8][4];
    #pragma unroll
    for (int nt = 0; nt < 8; nt++)
        o[nt][0] = o[nt][1] = o[nt][2] = o[nt][3] = 0.f;
    float m0r = -1e30f, m1r = -1e30f, l0r = 0.f, l1r = 0.f;

    cpa_wait0();
    __syncthreads();

    for (int kb = kb0; kb < kbE; kb++) {
        if (kb > kb0) { cpa_wait0(); __syncthreads(); }

        if (kb + 1 < kbE) {
            const int kn = (kb + 1) * 64;
            uint32_t sb    = sm_base + ((kb + 1) & 1) * STAGE_WORDS * 4;
            uint32_t kdst  = sb;
            uint32_t vtdst = sb + 64 * KT_S * 4;
            const uint32_t* ksrc  = kg  + (size_t)kn * DOUT;
            const uint32_t* vtsrc = vtg + (size_t)kn * DOUT;
            #pragma unroll
            for (int it = 0; it < 8; it++) {
                int row = ldrow + it * 8;
                cpa16(kdst  + (row * KT_S + ldc4) * 4, ksrc  + (size_t)row * DOUT + ldc4);
                cpa16(vtdst + (row * KT_S + ldc4) * 4, vtsrc + (size_t)row * DOUT + ldc4);
            }
            cpa_commit();
        }

        const uint32_t* Ks = sm + (kb & 1) * STAGE_WORDS;
        const uint32_t* VT = Ks + 64 * KT_S;

        // S = Q K^T
        float sf[8][4];
        #pragma unroll
        for (int nt = 0; nt < 8; nt++)
            sf[nt][0] = sf[nt][1] = sf[nt][2] = sf[nt][3] = 0.f;
        #pragma unroll
        for (int kc = 0; kc < 8; kc++) {
            #pragma unroll
            for (int nt = 0; nt < 8; nt++) {
                uint2 b = *(const uint2*)&Ks[(nt * 8 + lr) * KT_S + kc * 8 + 2 * lc];
                mma_tf32(sf[nt], qa[kc][0], qa[kc][1], qa[kc][2], qa[kc][3], b.x, b.y);
            }
        }

        // causal mask on the diagonal tile
        if (kb == qb) {
            int row0 = q0 + warp * 16 + lr;
            int row1 = row0 + 8;
            const int k0c = kb * 64;
            #pragma unroll
            for (int nt = 0; nt < 8; nt++) {
                int cb = k0c + nt * 8 + 2 * lc;
                if (cb     > row0) sf[nt][0] = -1e30f;
                if (cb + 1 > row0) sf[nt][1] = -1e30f;
                if (cb     > row1) sf[nt][2] = -1e30f;
                if (cb + 1 > row1) sf[nt][3] = -1e30f;
            }
        }

        // online softmax (exp2 space)
        float t0 = -1e30f, t1 = -1e30f;
        #pragma unroll
        for (int nt = 0; nt < 8; nt++) {
            t0 = fmaxf(t0, fmaxf(sf[nt][0], sf[nt][1]));
            t1 = fmaxf(t1, fmaxf(sf[nt][2], sf[nt][3]));
        }
        t0 = fmaxf(t0, __shfl_xor_sync(0xffffffffu, t0, 1));
        t0 = fmaxf(t0, __shfl_xor_sync(0xffffffffu, t0, 2));
        t1 = fmaxf(t1, __shfl_xor_sync(0xffffffffu, t1, 1));
        t1 = fmaxf(t1, __shfl_xor_sync(0xffffffffu, t1, 2));
        float mn0 = fmaxf(m0r, t0), mn1 = fmaxf(m1r, t1);
        float cor0 = ex2(m0r - mn0), cor1 = ex2(m1r - mn1);
        float rs0 = 0.f, rs1 = 0.f;
        #pragma unroll
        for (int nt = 0; nt < 8; nt++) {
            float p00 = ex2(sf[nt][0] - mn0), p01 = ex2(sf[nt][1] - mn0);
            float p10 = ex2(sf[nt][2] - mn1), p11 = ex2(sf[nt][3] - mn1);
            rs0 += p00 + p01; rs1 += p10 + p11;
            sf[nt][0] = __uint_as_float(f2tf(p00));
            sf[nt][1] = __uint_as_float(f2tf(p01));
            sf[nt][2] = __uint_as_float(f2tf(p10));
            sf[nt][3] = __uint_as_float(f2tf(p11));
            o[nt][0] *= cor0; o[nt][1] *= cor0;
            o[nt][2] *= cor1; o[nt][3] *= cor1;
        }
        rs0 += __shfl_xor_sync(0xffffffffu, rs0, 1);
        rs0 += __shfl_xor_sync(0xffffffffu, rs0, 2);
        rs1 += __shfl_xor_sync(0xffffffffu, rs1, 1);
        rs1 += __shfl_xor_sync(0xffffffffu, rs1, 2);
        l0r = l0r * cor0 + rs0; l1r = l1r * cor1 + rs1;
        m0r = mn0; m1r = mn1;

        // O += P V — P A-frags via quad shuffles
        #pragma unroll
        for (int kc = 0; kc < 8; kc++) {
            float s0 = __shfl_sync(0xffffffffu, sf[kc][0], srcA);
            float s1 = __shfl_sync(0xffffffffu, sf[kc][1], srcA);
            float s2 = __shfl_sync(0xffffffffu, sf[kc][2], srcA);
            float s3 = __shfl_sync(0xffffffffu, sf[kc][3], srcA);
            float u0 = __shfl_sync(0xffffffffu, sf[kc][0], srcB);
            float u1 = __shfl_sync(0xffffffffu, sf[kc][1], srcB);
            float u2 = __shfl_sync(0xffffffffu, sf[kc][2], srcB);
            float u3 = __shfl_sync(0xffffffffu, sf[kc][3], srcB);
            uint32_t a0 = __float_as_uint(odd ? s1 : s0);
            uint32_t a1 = __float_as_uint(odd ? s3 : s2);
            uint32_t a2 = __float_as_uint(odd ? u1 : u0);
            uint32_t a3 = __float_as_uint(odd ? u3 : u2);
            #pragma unroll
            for (int nt = 0; nt < 8; nt++) {
                uint2 b = *(const uint2*)&VT[(nt * 8 + lr) * KT_S + kc * 8 + 2 * lc];
                mma_tf32(o[nt], a0, a1, a2, a3, b.x, b.y);
            }
        }
    }

    if (nch == 1) {
        float inv0 = 1.f / l0r, inv1 = 1.f / l1r;
        #pragma unroll
        for (int nt = 0; nt < 8; nt++) {
            int col = nt * 8 + 2 * lc;
            size_t r0 = ((size_t)bb * SS + q0 + warp * 16 + lr) * DOUT + col;
            *(float2*)&out[r0]            = make_float2(o[nt][0] * inv0, o[nt][1] * inv0);
            *(float2*)&out[r0 + 8 * DOUT] = make_float2(o[nt][2] * inv1, o[nt][3] * inv1);
        }
    } else {
        const int slot = bb * SLOTS_PER_B + t;
        float* pO = g_pO + (size_t)slot * 64 * 64;
        const int lrow0 = warp * 16 + lr, lrow1 = lrow0 + 8;
        #pragma unroll
        for (int nt = 0; nt < 8; nt++) {
            int col = nt * 8 + 2 * lc;
            *(float2*)&pO[lrow0 * 64 + col] = make_float2(o[nt][0], o[nt][1]);
            *(float2*)&pO[lrow1 * 64 + col] = make_float2(o[nt][2], o[nt][3]);
        }
        if (lc == 0) {
            g_pm[slot * 64 + lrow0] = m0r;
            g_pm[slot * 64 + lrow1] = m1r;
            g_pl[slot * 64 + lrow0] = l0r;
            g_pl[slot * 64 + lrow1] = l1r;
        }
    }
}

// ---------------------------------------------------------------------------
// Combine partials for qb >= 8. Grid 896, 256 threads (one float4/thread).
// ---------------------------------------------------------------------------
__device__ __forceinline__ int slot_base(int qb) {
    if (qb < 8)  return qb;
    if (qb < 16) return 8   + (qb - 8)  * 2;
    if (qb < 24) return 24  + (qb - 16) * 3;
    if (qb < 32) return 48  + (qb - 24) * 4;
    if (qb < 40) return 80  + (qb - 32) * 5;
    if (qb < 48) return 120 + (qb - 40) * 6;
    if (qb < 56) return 168 + (qb - 48) * 7;
    return 224 + (qb - 56) * 8;
}

__global__ __launch_bounds__(256) void combine_kernel(float* __restrict__ out)
{
    const int idx = blockIdx.x;
    const int bb = idx & 3;
    const int qq = idx >> 2;              // 0..223
    const int qb = 8 + (qq >> 2);
    const int quarter = qq & 3;
    const int nch = (qb >> 3) + 1;
    const int base = bb * SLOTS_PER_B + slot_base(qb);

    const int row = quarter * 16 + (threadIdx.x >> 4);   // 0..63
    const int cg  = (threadIdx.x & 15) * 4;              // col group (float4)

    float mv[8], wv[8];
    float M = -1e30f;
    #pragma unroll 4
    for (int c = 0; c < nch; c++) {
        mv[c] = g_pm[(base + c) * 64 + row];
        M = fmaxf(M, mv[c]);
    }
    float L = 0.f;
    #pragma unroll 4
    for (int c = 0; c < nch; c++) {
        wv[c] = ex2(mv[c] - M);
        L += wv[c] * g_pl[(base + c) * 64 + row];
    }

    float4 acc = make_float4(0.f, 0.f, 0.f, 0.f);
    #pragma unroll 4
    for (int c = 0; c < nch; c++) {
        float4 v = *(const float4*)&g_pO[(size_t)(base + c) * 64 * 64 + row * 64 + cg];
        float w = wv[c];
        acc.x += w * v.x; acc.y += w * v.y;
        acc.z += w * v.z; acc.w += w * v.w;
    }
    float inv = 1.f / L;
    float* dst = out + ((size_t)bb * SS + qb * 64 + row) * DOUT + cg;
    *(float4*)dst = make_float4(acc.x * inv, acc.y * inv, acc.z * inv, acc.w * inv);
}

// ---------------------------------------------------------------------------
extern "C" void kernel_launch(void* const* d_in, const int* in_sizes, int n_in,
                              void* d_out, int out_size)
{
    const float* x  = (const float*)d_in[0];
    const float* Wq = (const float*)d_in[1];
    const float* Wk = (const float*)d_in[2];
    const float* Wv = (const float*)d_in[3];
    float* out = (float*)d_out;

    prep_w_kernel<<<dim3(384), 64>>>(Wq, Wk, Wv);

    cudaFuncSetAttribute(proj_kernel,
                         cudaFuncAttributeMaxDynamicSharedMemorySize,
                         PROJ_SMEM_BYTES);
    proj_kernel<<<dim3((BB * SS) / 64), 256, PROJ_SMEM_BYTES>>>(x);

    cudaFuncSetAttribute(attn_kernel,
                         cudaFuncAttributeMaxDynamicSharedMemorySize,
                         ATTN_SMEM_BYTES);
    attn_kernel<<<dim3(BB * SLOTS_PER_B), 128, ATTN_SMEM_BYTES>>>(out);

    combine_kernel<<<dim3(4 * 56 * 4), 256>>>(out);
}